// round 2
// baseline (speedup 1.0000x reference)
#include <cuda_runtime.h>
#include <cstddef>

#define B 16
#define N 1024
#define P 256
#define D 64
#define K 26

// ---- scratch (no allocations allowed; device globals) ----
__device__ float g_importance[N];          // [n]
__device__ float g_scores[B * P];          // [b, p]
__device__ float g_mean[B * P * D];        // [b, p, d]  (= patches.mean(axis=1))
__device__ int   g_topk[B * K];            // [b, k] sorted descending (stable)

// ------------------------------------------------------------------
// Kernel 1: importance[j] = mean_i adp[i, j]   (coalesced column sums)
// ------------------------------------------------------------------
__global__ void k_importance(const float* __restrict__ adp) {
    int j = blockIdx.x * blockDim.x + threadIdx.x;
    if (j >= N) return;
    float s = 0.f;
#pragma unroll 8
    for (int i = 0; i < N; i++) s += adp[(size_t)i * N + j];
    g_importance[j] = s * (1.0f / (float)N);
}

// ------------------------------------------------------------------
// Kernel 2: single fused pass over patches (the 1.07 GB read).
// One HALF-WARP per (b, p): 16 lanes x float4 = d=64.
// The two halves of a warp take adjacent p -> each warp LDG.128 is a
// fully coalesced contiguous 512B block.
// Produces: g_scores[b,p] = sum_n ||patches[b,n,p,:]|| * importance[n]
//           g_mean[b,p,:] = mean_n patches[b,n,p,:]
// ------------------------------------------------------------------
__global__ void __launch_bounds__(256) k_main(const float* __restrict__ patches) {
    int gwarp = (blockIdx.x * blockDim.x + threadIdx.x) >> 5;   // 0 .. B*P/2-1
    if (gwarp >= B * (P / 2)) return;
    int lane = threadIdx.x & 31;
    int half = lane >> 4;          // which p of the pair
    int hl   = lane & 15;          // lane within half-warp -> d-quarter

    int b  = gwarp / (P / 2);
    int p  = (gwarp % (P / 2)) * 2 + half;

    // patches[b, n, p, d]; base points at (b, 0, p, 4*hl) as float4
    const float4* base =
        (const float4*)(patches + (((size_t)b * N) * P + p) * (size_t)D) + hl;
    const size_t nstride = (size_t)P * D / 4;   // float4 stride per n

    float4 ms = make_float4(0.f, 0.f, 0.f, 0.f);
    float score = 0.f;

#pragma unroll 4
    for (int n = 0; n < N; n++) {
        float4 v = base[(size_t)n * nstride];
        ms.x += v.x; ms.y += v.y; ms.z += v.z; ms.w += v.w;
        float sq = v.x * v.x + v.y * v.y + v.z * v.z + v.w * v.w;
        // butterfly within the 16-lane half (offsets 8,4,2,1 stay in-half)
        sq += __shfl_xor_sync(0xffffffffu, sq, 8);
        sq += __shfl_xor_sync(0xffffffffu, sq, 4);
        sq += __shfl_xor_sync(0xffffffffu, sq, 2);
        sq += __shfl_xor_sync(0xffffffffu, sq, 1);
        score += sqrtf(sq) * g_importance[n];
    }

    const float inv = 1.0f / (float)N;
    ((float4*)g_mean)[((size_t)b * P + p) * (D / 4) + hl] =
        make_float4(ms.x * inv, ms.y * inv, ms.z * inv, ms.w * inv);
    if (hl == 0) g_scores[b * P + p] = score;
}

// ------------------------------------------------------------------
// Kernel 3: stable top-K per batch via rank counting.
// rank[p] = #{q : s[q] > s[p]  OR  (s[q]==s[p] AND q<p)}
// Matches jax.lax.top_k ordering (descending, lower index on ties).
// ------------------------------------------------------------------
__global__ void k_topk() {
    __shared__ float s[P];
    int b = blockIdx.x;
    int p = threadIdx.x;
    float my = g_scores[b * P + p];
    s[p] = my;
    __syncthreads();
    int rank = 0;
#pragma unroll 8
    for (int q = 0; q < P; q++) {
        float v = s[q];
        rank += (v > my) || (v == my && q < p);
    }
    if (rank < K) g_topk[b * K + rank] = p;
}

// ------------------------------------------------------------------
// Kernel 4: gather anchors for batch b into smem (26*64 floats = 6656B),
// then replicate to NN_PER_BLOCK n-slots with float4 stores.
// out[(b*N + nn)*K*D + k*D + d] = g_mean[b, topk[b,k], d]
// ------------------------------------------------------------------
#define NN_PER_BLOCK 16
#define KD4 (K * D / 4)   // 416 float4 per anchor block

__global__ void __launch_bounds__(256) k_out(float* __restrict__ out) {
    const int chunks = N / NN_PER_BLOCK;          // 64
    int b = blockIdx.x / chunks;
    int c = blockIdx.x % chunks;

    __shared__ float4 sa[KD4];
    for (int t = threadIdx.x; t < KD4; t += blockDim.x) {
        int kk  = t >> 4;          // /(D/4)
        int dd4 = t & 15;
        int pidx = g_topk[b * K + kk];
        sa[t] = ((const float4*)g_mean)[((size_t)b * P + pidx) * (D / 4) + dd4];
    }
    __syncthreads();

    float4* obase = (float4*)out + ((size_t)b * N + (size_t)c * NN_PER_BLOCK) * KD4;
#pragma unroll
    for (int nn = 0; nn < NN_PER_BLOCK; nn++) {
        float4* o = obase + (size_t)nn * KD4;
        for (int t = threadIdx.x; t < KD4; t += blockDim.x) o[t] = sa[t];
    }
}

// ------------------------------------------------------------------
extern "C" void kernel_launch(void* const* d_in, const int* in_sizes, int n_in,
                              void* d_out, int out_size) {
    const float* patches = (const float*)d_in[0];
    const float* adp     = (const float*)d_in[1];
    // defensive: metadata order is patches, adp — but verify by element count
    if (n_in >= 2 && in_sizes[0] == N * N && in_sizes[1] == B * N * P * D) {
        const float* t = patches; patches = adp; adp = t;
    }
    float* out = (float*)d_out;

    k_importance<<<(N + 255) / 256, 256>>>(adp);
    k_main<<<(B * (P / 2) * 32 + 255) / 256, 256>>>(patches);   // 2048 warps
    k_topk<<<B, P>>>();
    k_out<<<B * (N / NN_PER_BLOCK), 256>>>(out);
}

// round 3
// speedup vs baseline: 2.9166x; 2.9166x over previous
#include <cuda_runtime.h>
#include <cstddef>

#define B 16
#define N 1024
#define P 256
#define D 64
#define K 26
#define S 8                 // n-segments for k_main parallelism
#define NSEG (N / S)        // 128 n per segment

// ---- scratch (no allocations allowed; device globals) ----
__device__ float g_importance[N];            // [n]
__device__ float g_pscore[S * B * P];        // [s, b*P+p] partial scores
__device__ float g_pmean[S * B * P * D];     // [s, b*P+p, d] partial sums
__device__ float g_scores[B * P];            // [b, p]
__device__ float g_mean[B * P * D];          // [b, p, d]
__device__ int   g_topk[B * K];              // [b, k]

// ------------------------------------------------------------------
// Kernel 1: importance[j] = mean_i adp[i, j]
// ------------------------------------------------------------------
__global__ void k_importance(const float* __restrict__ adp) {
    int j = blockIdx.x * blockDim.x + threadIdx.x;
    if (j >= N) return;
    float s = 0.f;
#pragma unroll 8
    for (int i = 0; i < N; i++) s += adp[(size_t)i * N + j];
    g_importance[j] = s * (1.0f / (float)N);
}

// ------------------------------------------------------------------
// Kernel 2: fused streaming pass over patches, n-split into S segments.
// One HALF-WARP per (seg, b, p): 16 lanes x float4 = d=64; the two
// half-warps of a warp take adjacent p -> warp LDG.128s cover a fully
// contiguous 512B block per n. 16384 warps -> 2048 CTAs (all SMs hot).
// ------------------------------------------------------------------
__global__ void __launch_bounds__(256) k_main(const float* __restrict__ patches) {
    int gwarp = (blockIdx.x * blockDim.x + threadIdx.x) >> 5;   // 0 .. S*B*P/2-1
    if (gwarp >= S * B * (P / 2)) return;
    int lane = threadIdx.x & 31;
    int half = lane >> 4;
    int hl   = lane & 15;

    int seg   = gwarp / (B * (P / 2));
    int rem   = gwarp % (B * (P / 2));
    int b     = rem / (P / 2);
    int p     = (rem % (P / 2)) * 2 + half;
    int n0    = seg * NSEG;

    const float4* base =
        (const float4*)(patches + (((size_t)b * N + n0) * P + p) * (size_t)D) + hl;
    const size_t nstride = (size_t)P * D / 4;   // float4 per n

    float4 ms = make_float4(0.f, 0.f, 0.f, 0.f);
    float score = 0.f;

#pragma unroll 4
    for (int n = 0; n < NSEG; n++) {
        float4 v = __ldcs(base + (size_t)n * nstride);   // streaming, read-once
        ms.x += v.x; ms.y += v.y; ms.z += v.z; ms.w += v.w;
        float sq = v.x * v.x + v.y * v.y + v.z * v.z + v.w * v.w;
        sq += __shfl_xor_sync(0xffffffffu, sq, 8);
        sq += __shfl_xor_sync(0xffffffffu, sq, 4);
        sq += __shfl_xor_sync(0xffffffffu, sq, 2);
        sq += __shfl_xor_sync(0xffffffffu, sq, 1);
        score += sqrtf(sq) * g_importance[n0 + n];
    }

    size_t bp = (size_t)b * P + p;
    ((float4*)g_pmean)[((size_t)seg * B * P + bp) * (D / 4) + hl] = ms;
    if (hl == 0) g_pscore[(size_t)seg * B * P + bp] = score;
}

// ------------------------------------------------------------------
// Kernel 2b: deterministic reduce of the S partials.
//   g_mean  = (1/N) * sum_s pmean      (B*P*D/4 = 65536 float4 threads)
//   g_scores = sum_s pscore            (first B*P threads also do this)
// ------------------------------------------------------------------
__global__ void __launch_bounds__(256) k_reduce() {
    int t = blockIdx.x * blockDim.x + threadIdx.x;
    const int MF4 = B * P * D / 4;                 // 65536
    if (t < MF4) {
        float4 acc = make_float4(0.f, 0.f, 0.f, 0.f);
#pragma unroll
        for (int s = 0; s < S; s++) {
            float4 v = ((const float4*)g_pmean)[(size_t)s * MF4 + t];
            acc.x += v.x; acc.y += v.y; acc.z += v.z; acc.w += v.w;
        }
        const float inv = 1.0f / (float)N;
        ((float4*)g_mean)[t] = make_float4(acc.x * inv, acc.y * inv,
                                           acc.z * inv, acc.w * inv);
    }
    if (t < B * P) {
        float sc = 0.f;
#pragma unroll
        for (int s = 0; s < S; s++) sc += g_pscore[s * B * P + t];
        g_scores[t] = sc;
    }
}

// ------------------------------------------------------------------
// Kernel 3: stable top-K per batch via rank counting (matches
// jax.lax.top_k: descending, lower index wins ties).
// ------------------------------------------------------------------
__global__ void k_topk() {
    __shared__ float s[P];
    int b = blockIdx.x;
    int p = threadIdx.x;
    float my = g_scores[b * P + p];
    s[p] = my;
    __syncthreads();
    int rank = 0;
#pragma unroll 8
    for (int q = 0; q < P; q++) {
        float v = s[q];
        rank += (v > my) || (v == my && q < p);
    }
    if (rank < K) g_topk[b * K + rank] = p;
}

// ------------------------------------------------------------------
// Kernel 4: gather the 26x64 anchor block for batch b into registers
// (via smem), then replicate to NN_PER_BLOCK n-slots with float4 stores.
// ------------------------------------------------------------------
#define NN_PER_BLOCK 16
#define KD4 (K * D / 4)   // 416 float4 per anchor block

__global__ void __launch_bounds__(256) k_out(float* __restrict__ out) {
    const int chunks = N / NN_PER_BLOCK;          // 64
    int b = blockIdx.x / chunks;
    int c = blockIdx.x % chunks;

    __shared__ float4 sa[KD4];
    for (int t = threadIdx.x; t < KD4; t += blockDim.x) {
        int kk  = t >> 4;          // /(D/4)
        int dd4 = t & 15;
        int pidx = g_topk[b * K + kk];
        sa[t] = ((const float4*)g_mean)[((size_t)b * P + pidx) * (D / 4) + dd4];
    }
    __syncthreads();

    // cache this thread's slots in registers (<= 2 per thread)
    int t0 = threadIdx.x;
    int t1 = threadIdx.x + 256;
    float4 v0 = (t0 < KD4) ? sa[t0] : make_float4(0, 0, 0, 0);
    float4 v1 = (t1 < KD4) ? sa[t1] : make_float4(0, 0, 0, 0);

    float4* obase = (float4*)out + ((size_t)b * N + (size_t)c * NN_PER_BLOCK) * KD4;
#pragma unroll
    for (int nn = 0; nn < NN_PER_BLOCK; nn++) {
        float4* o = obase + (size_t)nn * KD4;
        o[t0] = v0;
        if (t1 < KD4) o[t1] = v1;
    }
}

// ------------------------------------------------------------------
extern "C" void kernel_launch(void* const* d_in, const int* in_sizes, int n_in,
                              void* d_out, int out_size) {
    const float* patches = (const float*)d_in[0];
    const float* adp     = (const float*)d_in[1];
    if (n_in >= 2 && in_sizes[0] == N * N && in_sizes[1] == B * N * P * D) {
        const float* t = patches; patches = adp; adp = t;
    }
    float* out = (float*)d_out;

    k_importance<<<(N + 255) / 256, 256>>>(adp);
    k_main<<<S * B * (P / 2) / 8, 256>>>(patches);      // 2048 CTAs, 16384 warps
    k_reduce<<<(B * P * D / 4 + 255) / 256, 256>>>();
    k_topk<<<B, P>>>();
    k_out<<<B * (N / NN_PER_BLOCK), 256>>>(out);
}

// round 4
// speedup vs baseline: 3.7810x; 1.2964x over previous
#include <cuda_runtime.h>
#include <cstddef>

#define B 16
#define N 1024
#define P 256
#define D 64
#define K 26
#define S 8                 // n-segments for k_main parallelism
#define NSEG (N / S)        // 128 n per segment

// ---- scratch (no allocations allowed; device globals) ----
__device__ float g_importance[N];            // [n]
__device__ float g_pimp[8 * N];              // [iseg, n] partial column sums
__device__ float g_pscore[S * B * P];        // [s, b*P+p] partial scores
__device__ float g_pmean[S * B * P * D];     // [s, b*P+p, d] partial sums
__device__ float g_scores[B * P];            // [b, p]
__device__ float g_mean[B * P * D];          // [b, p, d]
__device__ int   g_topk[B * K];              // [b, k]

// ------------------------------------------------------------------
// Kernel 1: importance[j] = mean_i adp[i, j]
// grid 32, block 256 = (32 j-cols) x (8 i-segments); smem reduce.
// ------------------------------------------------------------------
__global__ void __launch_bounds__(256) k_importance(const float* __restrict__ adp) {
    __shared__ float red[8][33];
    int jl   = threadIdx.x & 31;
    int iseg = threadIdx.x >> 5;             // 0..7
    int j    = blockIdx.x * 32 + jl;

    float s = 0.f;
    const float* col = adp + (size_t)(iseg * 128) * N + j;
#pragma unroll 8
    for (int i = 0; i < 128; i++) s += col[(size_t)i * N];
    red[iseg][jl] = s;
    __syncthreads();
    if (iseg == 0) {
        float t = 0.f;
#pragma unroll
        for (int r = 0; r < 8; r++) t += red[r][jl];
        g_importance[j] = t * (1.0f / (float)N);
    }
}

// ------------------------------------------------------------------
// Kernel 2: fused streaming pass over patches, n-split into S segments.
// One HALF-WARP per (seg, b, p): 16 lanes x float4 = d=64; the two
// half-warps of a warp take adjacent p -> warp LDG.128s cover a fully
// contiguous 512B block per n. 128-thread CTAs -> 4096 CTAs.
// ------------------------------------------------------------------
__global__ void __launch_bounds__(128) k_main(const float* __restrict__ patches) {
    int gwarp = (blockIdx.x * blockDim.x + threadIdx.x) >> 5;   // 0 .. S*B*P/2-1
    int lane = threadIdx.x & 31;
    int half = lane >> 4;
    int hl   = lane & 15;

    int seg   = gwarp / (B * (P / 2));
    int rem   = gwarp % (B * (P / 2));
    int b     = rem / (P / 2);
    int p     = (rem % (P / 2)) * 2 + half;
    int n0    = seg * NSEG;

    const float4* base =
        (const float4*)(patches + (((size_t)b * N + n0) * P + p) * (size_t)D) + hl;
    const size_t nstride = (size_t)P * D / 4;   // float4 per n
    const float* imp = g_importance + n0;

    float4 ms = make_float4(0.f, 0.f, 0.f, 0.f);
    float score = 0.f;

#pragma unroll 8
    for (int n = 0; n < NSEG; n++) {
        float4 v = __ldcs(base + (size_t)n * nstride);   // streaming, read-once
        ms.x += v.x; ms.y += v.y; ms.z += v.z; ms.w += v.w;
        float sq = v.x * v.x + v.y * v.y + v.z * v.z + v.w * v.w;
        sq += __shfl_xor_sync(0xffffffffu, sq, 8);
        sq += __shfl_xor_sync(0xffffffffu, sq, 4);
        sq += __shfl_xor_sync(0xffffffffu, sq, 2);
        sq += __shfl_xor_sync(0xffffffffu, sq, 1);
        score += sqrtf(sq) * __ldg(imp + n);
    }

    size_t bp = (size_t)b * P + p;
    ((float4*)g_pmean)[((size_t)seg * B * P + bp) * (D / 4) + hl] = ms;
    if (hl == 0) g_pscore[(size_t)seg * B * P + bp] = score;
}

// ------------------------------------------------------------------
// Kernel 2b: deterministic reduce of the S partials.
// ------------------------------------------------------------------
__global__ void __launch_bounds__(256) k_reduce() {
    int t = blockIdx.x * blockDim.x + threadIdx.x;
    const int MF4 = B * P * D / 4;                 // 65536
    if (t < MF4) {
        float4 acc = make_float4(0.f, 0.f, 0.f, 0.f);
#pragma unroll
        for (int s = 0; s < S; s++) {
            float4 v = ((const float4*)g_pmean)[(size_t)s * MF4 + t];
            acc.x += v.x; acc.y += v.y; acc.z += v.z; acc.w += v.w;
        }
        const float inv = 1.0f / (float)N;
        ((float4*)g_mean)[t] = make_float4(acc.x * inv, acc.y * inv,
                                           acc.z * inv, acc.w * inv);
    }
    if (t < B * P) {
        float sc = 0.f;
#pragma unroll
        for (int s = 0; s < S; s++) sc += g_pscore[s * B * P + t];
        g_scores[t] = sc;
    }
}

// ------------------------------------------------------------------
// Kernel 3: stable top-K per batch via 4-way-split rank counting.
// grid B, block 1024: p = tid>>2, each sub-thread counts 64 q's,
// combined with 2 shfl_xor (subs of one p are adjacent lanes).
// Matches jax.lax.top_k: descending, lower index wins ties.
// ------------------------------------------------------------------
__global__ void __launch_bounds__(1024) k_topk() {
    __shared__ float s[P];
    int b = blockIdx.x;
    int tid = threadIdx.x;
    if (tid < P) s[tid] = g_scores[b * P + tid];
    __syncthreads();

    int p   = tid >> 2;
    int sub = tid & 3;
    float my = s[p];
    int rank = 0;
    int q0 = sub * 64;
#pragma unroll 8
    for (int q = q0; q < q0 + 64; q++) {
        float v = s[q];
        rank += (v > my) || (v == my && q < p);
    }
    rank += __shfl_xor_sync(0xffffffffu, rank, 1);
    rank += __shfl_xor_sync(0xffffffffu, rank, 2);
    if (sub == 0 && rank < K) g_topk[b * K + rank] = p;
}

// ------------------------------------------------------------------
// Kernel 4: gather the 26x64 anchor block for batch b into registers
// (via smem), then replicate to NN_PER_BLOCK n-slots, streaming stores.
// ------------------------------------------------------------------
#define NN_PER_BLOCK 16
#define KD4 (K * D / 4)   // 416 float4 per anchor block

__global__ void __launch_bounds__(256) k_out(float* __restrict__ out) {
    const int chunks = N / NN_PER_BLOCK;          // 64
    int b = blockIdx.x / chunks;
    int c = blockIdx.x % chunks;

    __shared__ float4 sa[KD4];
    for (int t = threadIdx.x; t < KD4; t += blockDim.x) {
        int kk  = t >> 4;          // /(D/4)
        int dd4 = t & 15;
        int pidx = g_topk[b * K + kk];
        sa[t] = ((const float4*)g_mean)[((size_t)b * P + pidx) * (D / 4) + dd4];
    }
    __syncthreads();

    // cache this thread's slots in registers (<= 2 per thread)
    int t0 = threadIdx.x;
    int t1 = threadIdx.x + 256;
    float4 v0 = sa[t0];
    float4 v1 = (t1 < KD4) ? sa[t1] : make_float4(0, 0, 0, 0);

    float4* obase = (float4*)out + ((size_t)b * N + (size_t)c * NN_PER_BLOCK) * KD4;
#pragma unroll
    for (int nn = 0; nn < NN_PER_BLOCK; nn++) {
        float4* o = obase + (size_t)nn * KD4;
        __stcs(o + t0, v0);
        if (t1 < KD4) __stcs(o + t1, v1);
    }
}

// ------------------------------------------------------------------
extern "C" void kernel_launch(void* const* d_in, const int* in_sizes, int n_in,
                              void* d_out, int out_size) {
    const float* patches = (const float*)d_in[0];
    const float* adp     = (const float*)d_in[1];
    if (n_in >= 2 && in_sizes[0] == N * N && in_sizes[1] == B * N * P * D) {
        const float* t = patches; patches = adp; adp = t;
    }
    float* out = (float*)d_out;

    k_importance<<<32, 256>>>(adp);
    k_main<<<S * B * (P / 2) * 32 / 128, 128>>>(patches);   // 4096 CTAs
    k_reduce<<<(B * P * D / 4 + 255) / 256, 256>>>();
    k_topk<<<B, 1024>>>();
    k_out<<<B * (N / NN_PER_BLOCK), 256>>>(out);
}

// round 5
// speedup vs baseline: 3.9424x; 1.0427x over previous
#include <cuda_runtime.h>
#include <cstddef>

#define B 16
#define N 1024
#define P 256
#define D 64
#define K 26
#define S 4                 // n-segments for k_main parallelism
#define NSEG (N / S)        // 256 n per segment

// ---- scratch (no allocations allowed; device globals) ----
__device__ float g_importance[N];            // [n]
__device__ float g_pscore[S * B * P];        // [s, b*P+p] partial scores
__device__ float g_pmean[S * B * P * D];     // [s, b*P+p, d] partial sums
__device__ float g_mean[B * P * D];          // [b, p, d]
__device__ int   g_topk[B * K];              // [b, k]

// ------------------------------------------------------------------
// Kernel 1: importance[j] = mean_i adp[i, j]
// grid 32, block 256 = (32 j-cols) x (8 i-segments); smem reduce.
// ------------------------------------------------------------------
__global__ void __launch_bounds__(256) k_importance(const float* __restrict__ adp) {
    __shared__ float red[8][33];
    int jl   = threadIdx.x & 31;
    int iseg = threadIdx.x >> 5;             // 0..7
    int j    = blockIdx.x * 32 + jl;

    float s = 0.f;
    const float* col = adp + (size_t)(iseg * 128) * N + j;
#pragma unroll 8
    for (int i = 0; i < 128; i++) s += col[(size_t)i * N];
    red[iseg][jl] = s;
    __syncthreads();
    if (iseg == 0) {
        float t = 0.f;
#pragma unroll
        for (int r = 0; r < 8; r++) t += red[r][jl];
        g_importance[j] = t * (1.0f / (float)N);
    }
}

// ------------------------------------------------------------------
// Kernel 2: fused streaming pass over patches, n-split into S segments.
// One HALF-WARP per (seg, b, p): 16 lanes x float4 = d=64; the two
// half-warps of a warp take adjacent p -> warp LDG.128s cover a fully
// contiguous 512B block per n. 128-thread CTAs -> 2048 CTAs (1 wave).
// ------------------------------------------------------------------
__global__ void __launch_bounds__(128) k_main(const float* __restrict__ patches) {
    int gwarp = (blockIdx.x * blockDim.x + threadIdx.x) >> 5;   // 0 .. S*B*P/2-1
    int lane = threadIdx.x & 31;
    int half = lane >> 4;
    int hl   = lane & 15;

    int seg   = gwarp / (B * (P / 2));
    int rem   = gwarp % (B * (P / 2));
    int b     = rem / (P / 2);
    int p     = (rem % (P / 2)) * 2 + half;
    int n0    = seg * NSEG;

    const float4* base =
        (const float4*)(patches + (((size_t)b * N + n0) * P + p) * (size_t)D) + hl;
    const size_t nstride = (size_t)P * D / 4;   // float4 per n
    const float* imp = g_importance + n0;

    float4 ms = make_float4(0.f, 0.f, 0.f, 0.f);
    float score = 0.f;

#pragma unroll 8
    for (int n = 0; n < NSEG; n++) {
        float4 v = __ldcs(base + (size_t)n * nstride);   // streaming, read-once
        ms.x += v.x; ms.y += v.y; ms.z += v.z; ms.w += v.w;
        float sq = v.x * v.x + v.y * v.y + v.z * v.z + v.w * v.w;
        sq += __shfl_xor_sync(0xffffffffu, sq, 8);
        sq += __shfl_xor_sync(0xffffffffu, sq, 4);
        sq += __shfl_xor_sync(0xffffffffu, sq, 2);
        sq += __shfl_xor_sync(0xffffffffu, sq, 1);
        score += sqrtf(sq) * __ldg(imp + n);
    }

    size_t bp = (size_t)b * P + p;
    ((float4*)g_pmean)[((size_t)seg * B * P + bp) * (D / 4) + hl] = ms;
    if (hl == 0) g_pscore[(size_t)seg * B * P + bp] = score;
}

// ------------------------------------------------------------------
// Kernel 2b: deterministic reduce of the S partials + FUSED top-k.
// grid 256, block 256. All CTAs reduce their slice of g_pmean.
// CTA b < 16 additionally owns batch b's 256 scores (thread p):
// reduce pscore -> smem -> stable rank-count -> g_topk. Overlaps with
// the other 240 CTAs' mean work; removes the k_topk launch.
// Rank rule matches jax.lax.top_k: descending, lower index wins ties.
// ------------------------------------------------------------------
__global__ void __launch_bounds__(256) k_reduce() {
    __shared__ float sc[P];
    int t = blockIdx.x * blockDim.x + threadIdx.x;
    const int MF4 = B * P * D / 4;                 // 65536
    int b = blockIdx.x;                            // CTA id
    int p = threadIdx.x;

    // ---- mean reduce (all CTAs) ----
    if (t < MF4) {
        float4 acc = make_float4(0.f, 0.f, 0.f, 0.f);
#pragma unroll
        for (int s = 0; s < S; s++) {
            float4 v = ((const float4*)g_pmean)[(size_t)s * MF4 + t];
            acc.x += v.x; acc.y += v.y; acc.z += v.z; acc.w += v.w;
        }
        const float inv = 1.0f / (float)N;
        ((float4*)g_mean)[t] = make_float4(acc.x * inv, acc.y * inv,
                                           acc.z * inv, acc.w * inv);
    }

    // ---- fused score reduce + top-k (CTAs 0..15 only) ----
    if (b < B) {
        float my = 0.f;
#pragma unroll
        for (int s = 0; s < S; s++) my += g_pscore[s * B * P + b * P + p];
        sc[p] = my;
        __syncthreads();
        int rank = 0;
#pragma unroll 8
        for (int q = 0; q < P; q++) {
            float v = sc[q];
            rank += (v > my) || (v == my && q < p);
        }
        if (rank < K) g_topk[b * K + rank] = p;
    }
}

// ------------------------------------------------------------------
// Kernel 3: gather the 26x64 anchor block for batch b into registers
// (via smem), then replicate to NN_PER_BLOCK n-slots, streaming stores.
// ------------------------------------------------------------------
#define NN_PER_BLOCK 16
#define KD4 (K * D / 4)   // 416 float4 per anchor block

__global__ void __launch_bounds__(256) k_out(float* __restrict__ out) {
    const int chunks = N / NN_PER_BLOCK;          // 64
    int b = blockIdx.x / chunks;
    int c = blockIdx.x % chunks;

    __shared__ float4 sa[KD4];
    for (int t = threadIdx.x; t < KD4; t += blockDim.x) {
        int kk  = t >> 4;          // /(D/4)
        int dd4 = t & 15;
        int pidx = g_topk[b * K + kk];
        sa[t] = ((const float4*)g_mean)[((size_t)b * P + pidx) * (D / 4) + dd4];
    }
    __syncthreads();

    // cache this thread's slots in registers (<= 2 per thread)
    int t0 = threadIdx.x;
    int t1 = threadIdx.x + 256;
    float4 v0 = sa[t0];
    float4 v1 = (t1 < KD4) ? sa[t1] : make_float4(0, 0, 0, 0);

    float4* obase = (float4*)out + ((size_t)b * N + (size_t)c * NN_PER_BLOCK) * KD4;
#pragma unroll
    for (int nn = 0; nn < NN_PER_BLOCK; nn++) {
        float4* o = obase + (size_t)nn * KD4;
        __stcs(o + t0, v0);
        if (t1 < KD4) __stcs(o + t1, v1);
    }
}

// ------------------------------------------------------------------
extern "C" void kernel_launch(void* const* d_in, const int* in_sizes, int n_in,
                              void* d_out, int out_size) {
    const float* patches = (const float*)d_in[0];
    const float* adp     = (const float*)d_in[1];
    if (n_in >= 2 && in_sizes[0] == N * N && in_sizes[1] == B * N * P * D) {
        const float* t = patches; patches = adp; adp = t;
    }
    float* out = (float*)d_out;

    k_importance<<<32, 256>>>(adp);
    k_main<<<S * B * (P / 2) * 32 / 128, 128>>>(patches);   // 2048 CTAs
    k_reduce<<<256, 256>>>();                               // + fused top-k
    k_out<<<B * (N / NN_PER_BLOCK), 256>>>(out);
}